// round 1
// baseline (speedup 1.0000x reference)
#include <cuda_runtime.h>
#include <cuda_bf16.h>
#include <math.h>

#define FULLMASK 0xffffffffu

static const int N_ROI = 116;
static const int G     = 128;
static const int DEG   = 32;
static const int NN    = G * N_ROI;        // 14848 nodes
static const int EE    = G * N_ROI * DEG;  // 475136 edges
static const int EPG   = N_ROI * DEG;      // 3712 edges per graph
static const int HID   = 64;
static const int HC    = 256;
static const int MAXDEG = 192;

// ---------------- device scratch (allocation-free) ----------------
__device__ float g_h0[NN * HID];        // post-embed
__device__ float g_h1[NN * HID];        // post GINE+MLP+LN
__device__ float g_xl[NN * HC];
__device__ float g_xr[NN * HC];
__device__ float g_out[NN * HC];        // GAT layer output (in-place BN)
__device__ int   g_nodelist[NN * MAXDEG];
__device__ int   g_deg[NN];
__device__ float g_csum[HC];
__device__ float g_csq[HC];

// ---------------- adjacency build: warp per node, ordered ballot compaction ----
__global__ void build_adj_k(const int* __restrict__ dst) {
    int gw = (blockIdx.x * blockDim.x + threadIdx.x) >> 5;
    if (gw >= NN) return;
    int lane = threadIdx.x & 31;
    int n = gw;
    int g = n / N_ROI;
    int ebase = g * EPG;
    int count = 0;
    int* out = g_nodelist + n * MAXDEG;
    for (int i = 0; i < EPG; i += 32) {      // EPG divisible by 32
        int e = ebase + i + lane;
        int d = dst[e];
        unsigned m = __ballot_sync(FULLMASK, d == n);
        if (d == n) {
            int rank = __popc(m & ((1u << lane) - 1u));
            int pos = count + rank;
            if (pos < MAXDEG) out[pos] = e;
        }
        count += __popc(m);
    }
    if (lane == 0) g_deg[n] = min(count, MAXDEG);
}

// ---------------- node embed: concat(x, group_emb) @ W_embed, leaky 0.01 ------
__global__ void embed_k(const float* __restrict__ x, const int* __restrict__ node_group,
                        const float* __restrict__ gemb, const float* __restrict__ W,
                        const float* __restrict__ b) {
    int n = blockIdx.x;
    int t = threadIdx.x;   // 64
    __shared__ float sx[132];
    for (int i = t; i < 116; i += 64) sx[i] = x[n * 116 + i];
    if (t < 16) sx[116 + t] = gemb[node_group[n] * 16 + t];
    __syncthreads();
    float acc = b[t];
    #pragma unroll 4
    for (int r = 0; r < 132; r++) acc += sx[r] * W[r * 64 + t];
    g_h0[n * 64 + t] = acc >= 0.f ? acc : 0.01f * acc;
}

// ---------------- GINE aggregate + MLP + LayerNorm (block per node, 64 thr) ---
__global__ void gine_k(const int* __restrict__ srcA, const float* __restrict__ ea,
                       const float* __restrict__ We, const float* __restrict__ be,
                       const float* __restrict__ W1, const float* __restrict__ b1,
                       const float* __restrict__ W2, const float* __restrict__ b2,
                       const float* __restrict__ lng, const float* __restrict__ lnb) {
    int n = blockIdx.x;
    int t = threadIdx.x;   // 64
    __shared__ float sh[64], sh2[64], ws[2], wq[2];
    float s = g_h0[n * 64 + t];
    int d = g_deg[n];
    const int* lst = g_nodelist + n * MAXDEG;
    float bec = be[t];
    float w0 = We[t], w1 = We[64 + t], w2 = We[128 + t], w3 = We[192 + t], w4 = We[256 + t];
    for (int i = 0; i < d; i++) {
        int e = lst[i];
        int src = srcA[e];
        const float* a = ea + (long)e * 5;
        float em = bec + a[0] * w0 + a[1] * w1 + a[2] * w2 + a[3] * w3 + a[4] * w4;
        em = em >= 0.f ? em : 0.01f * em;                 // leaky edge encoder
        float v = g_h0[src * 64 + t] + em;
        s += v > 0.f ? v : 0.f;                           // relu message
    }
    sh[t] = s;
    __syncthreads();
    float acc = b1[t];
    #pragma unroll 8
    for (int r = 0; r < 64; r++) acc += sh[r] * W1[r * 64 + t];
    acc = acc >= 0.f ? acc : 0.01f * acc;
    sh2[t] = acc;
    __syncthreads();
    float acc2 = b2[t];
    #pragma unroll 8
    for (int r = 0; r < 64; r++) acc2 += sh2[r] * W2[r * 64 + t];
    acc2 = acc2 >= 0.f ? acc2 : 0.01f * acc2;
    // LayerNorm over 64
    float su = acc2, sq = acc2 * acc2;
    for (int o = 16; o; o >>= 1) {
        su += __shfl_down_sync(FULLMASK, su, o);
        sq += __shfl_down_sync(FULLMASK, sq, o);
    }
    if ((t & 31) == 0) { ws[t >> 5] = su; wq[t >> 5] = sq; }
    __syncthreads();
    float mu  = (ws[0] + ws[1]) * (1.f / 64.f);
    float var = (wq[0] + wq[1]) * (1.f / 64.f) - mu * mu;
    g_h1[n * 64 + t] = (acc2 - mu) * rsqrtf(var + 1e-5f) * lng[t] + lnb[t];
}

// ---------------- xl/xr projections, 16 nodes per block ------------------------
template <int LAYER>
__global__ void xlxr_k(const float* __restrict__ Wl, const float* __restrict__ Wr) {
    constexpr int D = LAYER ? HC : HID;
    const float* hin = LAYER ? g_out : g_h1;
    int nb = blockIdx.x * 16;
    int t = threadIdx.x;   // 256
    __shared__ float sh[16][D];
    for (int i = t; i < 16 * D; i += 256) {
        int nn = i / D, c = i % D;
        sh[nn][c] = hin[(nb + nn) * D + c];
    }
    __syncthreads();
    float al[16], ar[16];
    #pragma unroll
    for (int j = 0; j < 16; j++) { al[j] = 0.f; ar[j] = 0.f; }
    for (int r = 0; r < D; r++) {
        float wl = Wl[r * 256 + t], wr = Wr[r * 256 + t];
        #pragma unroll
        for (int j = 0; j < 16; j++) {
            float hv = sh[j][r];
            al[j] += hv * wl;
            ar[j] += hv * wr;
        }
    }
    #pragma unroll
    for (int j = 0; j < 16; j++) {
        g_xl[(nb + j) * 256 + t] = al[j];
        g_xr[(nb + j) * 256 + t] = ar[j];
    }
}

// ---------------- fused GATv2: logits + softmax + aggregate (block per node) ---
__global__ void gat_node_k(const int* __restrict__ srcA, const float* __restrict__ ea,
                           const float* __restrict__ WeP,   // [5,256]
                           const float* __restrict__ attF)  // [4*64] flattened
{
    int n = blockIdx.x;
    int t = threadIdx.x;     // 256
    int lane = t & 31, wid = t >> 5;
    int hh = wid & 3, epair = wid >> 2;
    __shared__ float sxr[256];
    __shared__ float slog[MAXDEG * 4];
    __shared__ int   ssrc[MAXDEG];
    sxr[t] = g_xr[n * 256 + t];
    __syncthreads();
    int d = g_deg[n];
    const int* lst = g_nodelist + n * MAXDEG;
    int k1 = hh * 64 + lane, k2 = k1 + 32;
    float a1 = attF[k1], a2 = attF[k2];
    // phase 1: warp per (edge, head) computes attention logit
    for (int i = epair; i < d; i += 2) {
        int e = lst[i];
        int s = srcA[e];
        const float* a = ea + (long)e * 5;
        float e0 = a[0], e1 = a[1], e2 = a[2], e3 = a[3], e4 = a[4];
        float ep1 = e0 * WeP[k1] + e1 * WeP[256 + k1] + e2 * WeP[512 + k1]
                  + e3 * WeP[768 + k1] + e4 * WeP[1024 + k1];
        float ep2 = e0 * WeP[k2] + e1 * WeP[256 + k2] + e2 * WeP[512 + k2]
                  + e3 * WeP[768 + k2] + e4 * WeP[1024 + k2];
        float z1 = g_xl[s * 256 + k1] + sxr[k1] + ep1;
        float z2 = g_xl[s * 256 + k2] + sxr[k2] + ep2;
        z1 = z1 >= 0.f ? z1 : 0.2f * z1;
        z2 = z2 >= 0.f ? z2 : 0.2f * z2;
        float v = z1 * a1 + z2 * a2;
        for (int o = 16; o; o >>= 1) v += __shfl_down_sync(FULLMASK, v, o);
        if (lane == 0) {
            slog[i * 4 + hh] = v;
            if (hh == 0) ssrc[i] = s;
        }
    }
    __syncthreads();
    // phase 2: softmax over in-edges per head (4 threads, ~deg work each)
    if (t < 4) {
        float m = -1e30f;
        for (int i = 0; i < d; i++) m = fmaxf(m, slog[i * 4 + t]);
        float ssum = 0.f;
        for (int i = 0; i < d; i++) {
            float ex = expf(slog[i * 4 + t] - m);
            slog[i * 4 + t] = ex;
            ssum += ex;
        }
        float inv = 1.f / (ssum + 1e-16f);
        for (int i = 0; i < d; i++) slog[i * 4 + t] *= inv;
    }
    __syncthreads();
    // phase 3: weighted aggregation (xl rows are L1-hot from phase 1)
    int h = t >> 6;
    float acc = 0.f;
    for (int i = 0; i < d; i++)
        acc += g_xl[ssrc[i] * 256 + t] * slog[i * 4 + h];
    g_out[n * 256 + t] = acc;   // GAT bias absorbed by BatchNorm — skipped
}

// ---------------- BatchNorm: stats + apply ------------------------------------
__global__ void zero_stats_k() {
    int t = threadIdx.x;
    g_csum[t] = 0.f;
    g_csq[t]  = 0.f;
}

__global__ void bnstat_k() {
    int t = threadIdx.x;  // 256 = channel
    int rows = (NN + gridDim.x - 1) / gridDim.x;
    int r0 = blockIdx.x * rows;
    int r1 = min(NN, r0 + rows);
    float s = 0.f, q = 0.f;
    for (int r = r0; r < r1; r++) {
        float v = g_out[r * 256 + t];
        s += v;
        q += v * v;
    }
    atomicAdd(&g_csum[t], s);
    atomicAdd(&g_csq[t], q);
}

__global__ void bnapply_k(const float* __restrict__ gam, const float* __restrict__ bet) {
    int k = threadIdx.x;                 // channel
    int idx = blockIdx.x * 256 + k;      // grid = NN
    float mu  = g_csum[k] * (1.f / NN);
    float var = g_csq[k] * (1.f / NN) - mu * mu;
    float v = g_out[idx];
    v = (v - mu) * rsqrtf(var + 1e-5f) * gam[k] + bet[k];
    g_out[idx] = v >= 0.f ? v : 0.01f * v;
}

// ---------------- pool + classifier -------------------------------------------
__global__ void pool_k(const float* __restrict__ W, const float* __restrict__ bb,
                       float* __restrict__ outp) {
    int g = blockIdx.x;   // 128 graphs
    int t = threadIdx.x;  // 256
    float s = 0.f;
    int base = g * N_ROI;
    for (int r = 0; r < N_ROI; r++) s += g_out[(base + r) * 256 + t];
    s *= (1.f / (float)N_ROI);
    float c0 = s * W[t * 2], c1 = s * W[t * 2 + 1];
    __shared__ float r0[8], r1[8];
    for (int o = 16; o; o >>= 1) {
        c0 += __shfl_down_sync(FULLMASK, c0, o);
        c1 += __shfl_down_sync(FULLMASK, c1, o);
    }
    if ((t & 31) == 0) { r0[t >> 5] = c0; r1[t >> 5] = c1; }
    __syncthreads();
    if (t == 0) {
        float a = 0.f, b2 = 0.f;
        for (int i = 0; i < 8; i++) { a += r0[i]; b2 += r1[i]; }
        outp[g * 2]     = a  + bb[0];
        outp[g * 2 + 1] = b2 + bb[1];
    }
}

// ---------------- launch --------------------------------------------------------
extern "C" void kernel_launch(void* const* d_in, const int* in_sizes, int n_in,
                              void* d_out, int out_size) {
    const float* x          = (const float*)d_in[0];
    const int*   edge_index = (const int*)  d_in[1];
    const float* edge_attr  = (const float*)d_in[2];
    // d_in[3] = batch (implicit via contiguous layout)
    const int*   node_group = (const int*)  d_in[4];
    const float* group_emb  = (const float*)d_in[5];
    const float* W_embed    = (const float*)d_in[6];
    const float* b_embed    = (const float*)d_in[7];
    const float* We_enc     = (const float*)d_in[8];
    const float* be_enc     = (const float*)d_in[9];
    const float* W1         = (const float*)d_in[10];
    const float* b1         = (const float*)d_in[11];
    const float* W2         = (const float*)d_in[12];
    const float* b2         = (const float*)d_in[13];
    const float* ln_g       = (const float*)d_in[14];
    const float* ln_b       = (const float*)d_in[15];
    const float* l0_Wl      = (const float*)d_in[16];
    const float* l0_Wr      = (const float*)d_in[17];
    const float* l0_We      = (const float*)d_in[18];
    const float* l0_att     = (const float*)d_in[19];
    // d_in[20] = l0_b (absorbed by BN)
    const float* l0_bn_g    = (const float*)d_in[21];
    const float* l0_bn_b    = (const float*)d_in[22];
    const float* l1_Wl      = (const float*)d_in[23];
    const float* l1_Wr      = (const float*)d_in[24];
    const float* l1_We      = (const float*)d_in[25];
    const float* l1_att     = (const float*)d_in[26];
    // d_in[27] = l1_b (absorbed by BN)
    const float* l1_bn_g    = (const float*)d_in[28];
    const float* l1_bn_b    = (const float*)d_in[29];
    const float* fc2_W      = (const float*)d_in[30];
    const float* fc2_b      = (const float*)d_in[31];

    const int* srcp = edge_index;
    const int* dstp = edge_index + EE;

    build_adj_k<<<(NN * 32 + 255) / 256, 256>>>(dstp);
    embed_k<<<NN, 64>>>(x, node_group, group_emb, W_embed, b_embed);
    gine_k<<<NN, 64>>>(srcp, edge_attr, We_enc, be_enc, W1, b1, W2, b2, ln_g, ln_b);

    // GAT layer 0
    xlxr_k<0><<<NN / 16, 256>>>(l0_Wl, l0_Wr);
    gat_node_k<<<NN, 256>>>(srcp, edge_attr, l0_We, l0_att);
    zero_stats_k<<<1, 256>>>();
    bnstat_k<<<256, 256>>>();
    bnapply_k<<<NN, 256>>>(l0_bn_g, l0_bn_b);

    // GAT layer 1
    xlxr_k<1><<<NN / 16, 256>>>(l1_Wl, l1_Wr);
    gat_node_k<<<NN, 256>>>(srcp, edge_attr, l1_We, l1_att);
    zero_stats_k<<<1, 256>>>();
    bnstat_k<<<256, 256>>>();
    bnapply_k<<<NN, 256>>>(l1_bn_g, l1_bn_b);

    pool_k<<<G, 256>>>(fc2_W, fc2_b, (float*)d_out);
}